// round 16
// baseline (speedup 1.0000x reference)
#include <cuda_runtime.h>
#include <cuda_fp16.h>
#include <math.h>

// ---------------------------------------------------------------------------
// Problem constants
// ---------------------------------------------------------------------------
#define BB   2
#define SS   2048
#define HH   1024
#define NHH  16
#define HDD  64
#define MM   (BB*SS)      // 4096
#define KK   1024

// k-permutation within each 16-group: thread j's m16n8k16 fragment halves
// {2j,2j+1,2j+8,2j+9} become contiguous -> single 8B load per fragment.
#define KPOS(k) ((((k)&6)<<1) + ((((k)>>3)&1)<<1) + ((k)&1))

// Scratch (device globals) — fp16, k-permuted where contracted
__device__ __half g_q[BB*NHH*SS*HDD];     // [b,h,s,d] d-permuted, pre-scaled
__device__ __half g_k[BB*NHH*SS*HDD];     // [b,h,s,d] d-permuted
__device__ __half g_vt[BB*NHH*HDD*SS];    // [b,h,d,s] s-permuted
__device__ __half g_attn[BB*NHH*SS*HDD];  // [b,h,s,d] d-permuted
__device__ __half g_hs[MM*KK];            // [m][k]    k-permuted
__device__ __half g_wqt[HH*KK];           // [n][k]    k-permuted
__device__ __half g_wkt[HH*KK];
__device__ __half g_wvt[HH*KK];
__device__ __half g_wot[HH*KK];
__device__ float  g_cost[SS*32];
__device__ float  g_sint[SS*32];

// ---------------------------------------------------------------------------
// Helpers
// ---------------------------------------------------------------------------
__device__ __forceinline__ unsigned pack_h2(float lo, float hi) {
    unsigned r;
    asm("cvt.rn.f16x2.f32 %0, %1, %2;" : "=r"(r) : "f"(hi), "f"(lo));
    return r;
}
__device__ __forceinline__ unsigned ex2h2(unsigned x) {
    unsigned r;
    asm("ex2.approx.f16x2 %0, %1;" : "=r"(r) : "r"(x));
    return r;
}
__device__ __forceinline__ void mma_f16(float& c0, float& c1, float& c2, float& c3,
                                        unsigned a0, unsigned a1, unsigned a2, unsigned a3,
                                        unsigned b0, unsigned b1) {
    asm volatile(
        "mma.sync.aligned.m16n8k16.row.col.f32.f16.f16.f32 "
        "{%0,%1,%2,%3}, {%4,%5,%6,%7}, {%8,%9}, {%0,%1,%2,%3};"
        : "+f"(c0), "+f"(c1), "+f"(c2), "+f"(c3)
        : "r"(a0), "r"(a1), "r"(a2), "r"(a3), "r"(b0), "r"(b1));
}
__device__ __forceinline__ unsigned smem_u32(const void* p) {
    unsigned a;
    asm("{ .reg .u64 t; cvta.to.shared.u64 t, %1; cvt.u32.u64 %0, t; }"
        : "=r"(a) : "l"(p));
    return a;
}
__device__ __forceinline__ void cp16(unsigned s, const void* g) {
    asm volatile("cp.async.cg.shared.global [%0], [%1], 16;" :: "r"(s), "l"(g));
}
#define CP_COMMIT() asm volatile("cp.async.commit_group;" ::: "memory")
#define CP_WAIT0()  asm volatile("cp.async.wait_group 0;" ::: "memory")

// ---------------------------------------------------------------------------
// Prep: hidden fp32 -> fp16 k-permuted; RoPE table
// ---------------------------------------------------------------------------
__global__ void prep_kernel(const float* __restrict__ hs) {
    int i = blockIdx.x * blockDim.x + threadIdx.x;   // 0..262143
    const float4* src = (const float4*)(hs + (size_t)i * 16);
    float4 v0 = src[0], v1 = src[1], v2 = src[2], v3 = src[3];
    uint4 o0, o1;
    o0.x = pack_h2(v0.x, v0.y);   // pos 0,1   = k0,1
    o0.y = pack_h2(v2.x, v2.y);   // pos 2,3   = k8,9
    o0.z = pack_h2(v0.z, v0.w);   // pos 4,5   = k2,3
    o0.w = pack_h2(v2.z, v2.w);   // pos 6,7   = k10,11
    o1.x = pack_h2(v1.x, v1.y);   // pos 8,9   = k4,5
    o1.y = pack_h2(v3.x, v3.y);   // pos 10,11 = k12,13
    o1.z = pack_h2(v1.z, v1.w);   // pos 12,13 = k6,7
    o1.w = pack_h2(v3.z, v3.w);   // pos 14,15 = k14,15
    uint4* dst = (uint4*)(g_hs + (size_t)i * 16);
    dst[0] = o0; dst[1] = o1;

    if (i < SS * 32) {
        int s = i >> 5, j = i & 31;
        float inv = expf(-((float)(2 * j) / 64.0f) * 9.210340371976184f);
        float ang = (float)s * inv;
        float c, sn;
        sincosf(ang, &sn, &c);
        g_cost[i] = c;
        g_sint[i] = sn;
    }
}

// ---------------------------------------------------------------------------
// Transpose + fp16 + k-permute the 4 weight matrices: [k][n] -> [n][k]
// ---------------------------------------------------------------------------
__global__ void pre_round_w(const float* __restrict__ wq, const float* __restrict__ wk,
                            const float* __restrict__ wv, const float* __restrict__ wo) {
    __shared__ float t[32][33];
    const int z = blockIdx.z;
    const float* src = (z == 0) ? wq : (z == 1) ? wk : (z == 2) ? wv : wo;
    __half* dst = (z == 0) ? g_wqt : (z == 1) ? g_wkt : (z == 2) ? g_wvt : g_wot;
    const int k0 = blockIdx.x * 32, n0 = blockIdx.y * 32;
    #pragma unroll
    for (int i = 0; i < 4; i++) {
        int ky = threadIdx.y + i * 8;
        t[ky][threadIdx.x] = src[(size_t)(k0 + ky) * HH + n0 + threadIdx.x];
    }
    __syncthreads();
    int kx = threadIdx.x;
    int kp = k0 + (kx & ~15) + KPOS(kx & 15);
    #pragma unroll
    for (int i = 0; i < 4; i++) {
        int ny = threadIdx.y + i * 8;
        dst[(size_t)(n0 + ny) * KK + kp] = __float2half_rn(t[kx][ny]);
    }
}

// ---------------------------------------------------------------------------
// fp16 mma GEMM (unchanged from R14): 128x128 CTA tile (2 heads), k-chunk 64,
// 128 threads, 4 warps x (64x64), 2-stage cp.async, 128 MMAs per wait.
// ---------------------------------------------------------------------------
#define RSTB 176                          // row stride bytes (88 halves)
#define ASTAGE_B (128*RSTB)               // 22528
#define BSTAGE_B (128*RSTB)               // 22528
#define STAGE_B  (ASTAGE_B + BSTAGE_B)    // 45056
#define GEMM_SMEM (2 * STAGE_B)           // 90112
#define CST 132

__device__ __forceinline__ void gemm_chunk_f16(const char* As, const char* Bs,
                                               float acc[4][8][4],
                                               int wm, int wn, int g, int j) {
    #pragma unroll
    for (int kg = 0; kg < 4; kg++) {
        const int kb = (kg * 16 + 4 * j) * 2;
        uint2 a[4][2], bv[8];
        #pragma unroll
        for (int mt = 0; mt < 4; mt++) {
            int r = wm * 64 + mt * 16 + g;
            a[mt][0] = *(const uint2*)(As + r * RSTB + kb);
            a[mt][1] = *(const uint2*)(As + (r + 8) * RSTB + kb);
        }
        #pragma unroll
        for (int nt = 0; nt < 8; nt++) {
            int rr = wn * 64 + nt * 8 + g;
            bv[nt] = *(const uint2*)(Bs + rr * RSTB + kb);
        }
        #pragma unroll
        for (int mt = 0; mt < 4; mt++)
            #pragma unroll
            for (int nt = 0; nt < 8; nt++)
                mma_f16(acc[mt][nt][0], acc[mt][nt][1], acc[mt][nt][2], acc[mt][nt][3],
                        a[mt][0].x, a[mt][1].x, a[mt][0].y, a[mt][1].y,
                        bv[nt].x, bv[nt].y);
    }
}

// which: 0=q(rope,scaled) 1=k(rope) 2=v(transposed). n-tile = TWO heads.
__global__ __launch_bounds__(128) void qkv_mma(
    const float* __restrict__ bq, const float* __restrict__ bk, const float* __restrict__ bv)
{
    extern __shared__ char smc[];
    const int which = blockIdx.z;
    const __half* WT  = (which == 0) ? g_wqt : (which == 1) ? g_wkt : g_wvt;
    const float* bias = (which == 0) ? bq    : (which == 1) ? bk    : bv;

    const int head0 = blockIdx.x * 2;
    const int n0 = head0 * 64, m0 = blockIdx.y * 128;
    const int tid = threadIdx.x, wid = tid >> 5, lane = tid & 31;
    const int g = lane >> 2, j = lane & 3;
    const int wm = wid & 1, wn = wid >> 1;
    const unsigned sb = smem_u32(smc);

    auto stage = [&](int c) {
        const int k0 = c * 64;
        const unsigned bufb = sb + (c & 1) * STAGE_B;
        #pragma unroll
        for (int i = 0; i < 8; i++) {
            int idx = tid + i * 128, r = idx >> 3, c8 = idx & 7;
            cp16(bufb + r * RSTB + c8 * 16, &g_hs[(size_t)(m0 + r) * KK + k0 + c8 * 8]);
        }
        #pragma unroll
        for (int i = 0; i < 8; i++) {
            int idx = tid + i * 128, r = idx >> 3, c8 = idx & 7;
            cp16(bufb + ASTAGE_B + r * RSTB + c8 * 16,
                 &WT[(size_t)(n0 + r) * KK + k0 + c8 * 8]);
        }
        CP_COMMIT();
    };

    float acc[4][8][4] = {};
    stage(0);
    for (int c = 0; c < 16; c++) {
        CP_WAIT0();
        __syncthreads();
        if (c < 15) stage(c + 1);
        const char* As = smc + (c & 1) * STAGE_B;
        gemm_chunk_f16(As, As + ASTAGE_B, acc, wm, wn, g, j);
    }
    __syncthreads();

    float* Cs = (float*)smc;
    #pragma unroll
    for (int mt = 0; mt < 4; mt++)
        #pragma unroll
        for (int nt = 0; nt < 8; nt++) {
            int r = wm * 64 + mt * 16 + g, cc = wn * 64 + nt * 8 + 2 * j;
            *(float2*)&Cs[r * CST + cc]       = make_float2(acc[mt][nt][0], acc[mt][nt][1]);
            *(float2*)&Cs[(r + 8) * CST + cc] = make_float2(acc[mt][nt][2], acc[mt][nt][3]);
        }
    __syncthreads();

    const float QSCALE = 0.125f * 1.4426950408889634f;
    if (which != 2) {
        __half* out = (which == 0) ? g_q : g_k;
        const float scale = (which == 0) ? QSCALE : 1.0f;
        #pragma unroll 4
        for (int it = 0; it < 64; it++) {
            int p = it * 128 + tid;          // 128 rows x 64 pairs
            int r = p >> 6, hh = (p >> 5) & 1, jj = p & 31;
            int m = m0 + r, bb = m >> 11, s = m & 2047;
            int head = head0 + hh;
            float x1 = Cs[r * CST + hh * 64 + jj]      + bias[head * 64 + jj];
            float x2 = Cs[r * CST + hh * 64 + jj + 32] + bias[head * 64 + jj + 32];
            float cs = g_cost[s * 32 + jj], sn = g_sint[s * 32 + jj];
            __half* op = out + ((size_t)(bb * NHH + head) * SS + s) * HDD;
            int d1 = jj, d2 = jj + 32;
            op[(d1 & ~15) + KPOS(d1 & 15)] = __float2half_rn((x1 * cs - x2 * sn) * scale);
            op[(d2 & ~15) + KPOS(d2 & 15)] = __float2half_rn((x1 * sn + x2 * cs) * scale);
        }
    } else {
        #pragma unroll 4
        for (int it = 0; it < 128; it++) {
            int p = it * 128 + tid;          // 128 cols x 128 rows
            int r = p & 127, cc = p >> 7;
            int m = m0 + r, bb = m >> 11, s = m & 2047;
            int head = head0 + (cc >> 6), d = cc & 63;
            int spos = (s & ~15) + KPOS(s & 15);
            g_vt[((size_t)(bb * NHH + head) * HDD + d) * SS + spos] =
                __float2half_rn(Cs[r * CST + cc] + bias[head * 64 + d]);
        }
    }
}

__global__ __launch_bounds__(128) void proj_mma(
    const float* __restrict__ bo, float* __restrict__ outp)
{
    extern __shared__ char smc[];
    const int n0 = blockIdx.x * 128, m0 = blockIdx.y * 128;
    const int tid = threadIdx.x, wid = tid >> 5, lane = tid & 31;
    const int g = lane >> 2, j = lane & 3;
    const int wm = wid & 1, wn = wid >> 1;
    const unsigned sb = smem_u32(smc);

    auto stage = [&](int c) {
        const unsigned bufb = sb + (c & 1) * STAGE_B;
        #pragma unroll
        for (int i = 0; i < 8; i++) {
            int idx = tid + i * 128, r = idx >> 3, c8 = idx & 7;
            int m = m0 + r, bb = m >> 11, s = m & 2047;
            cp16(bufb + r * RSTB + c8 * 16,
                 &g_attn[((size_t)(bb * NHH + c) * SS + s) * HDD + c8 * 8]);
        }
        #pragma unroll
        for (int i = 0; i < 8; i++) {
            int idx = tid + i * 128, r = idx >> 3, c8 = idx & 7;
            cp16(bufb + ASTAGE_B + r * RSTB + c8 * 16,
                 &g_wot[(size_t)(n0 + r) * KK + c * 64 + c8 * 8]);
        }
        CP_COMMIT();
    };

    float acc[4][8][4] = {};
    stage(0);
    for (int c = 0; c < 16; c++) {
        CP_WAIT0();
        __syncthreads();
        if (c < 15) stage(c + 1);
        const char* As = smc + (c & 1) * STAGE_B;
        gemm_chunk_f16(As, As + ASTAGE_B, acc, wm, wn, g, j);
    }
    __syncthreads();

    float* Cs = (float*)smc;
    #pragma unroll
    for (int mt = 0; mt < 4; mt++)
        #pragma unroll
        for (int nt = 0; nt < 8; nt++) {
            int r = wm * 64 + mt * 16 + g, cc = wn * 64 + nt * 8 + 2 * j;
            *(float2*)&Cs[r * CST + cc]       = make_float2(acc[mt][nt][0], acc[mt][nt][1]);
            *(float2*)&Cs[(r + 8) * CST + cc] = make_float2(acc[mt][nt][2], acc[mt][nt][3]);
        }
    __syncthreads();

    #pragma unroll 4
    for (int i = 0; i < 32; i++) {
        int idx = tid + i * 128;             // 128 rows x 32 float4
        int r = idx >> 5, c4 = idx & 31;
        float4 v = *(float4*)&Cs[r * CST + c4 * 4];
        float4 bv = *(const float4*)&bo[n0 + c4 * 4];
        v.x += bv.x; v.y += bv.y; v.z += bv.z; v.w += bv.w;
        *(float4*)&outp[(size_t)(m0 + r) * HH + n0 + c4 * 4] = v;
    }
}

// ---------------------------------------------------------------------------
// Flash attention fp16 v3: Q fragments loaded DIRECTLY FROM GLOBAL (no Q in
// smem at all) -> smem 47.9KB -> 4 CTAs/SM at <=128 regs. Fused S->exp->PV,
// tensor-core l (ones-column), f16x2 exp.
// ---------------------------------------------------------------------------
#define KB 0                               // K: 2 x 64 rows
#define VB (2*64*RSTB)                     // V: 2 x 72 rows (64 data + ones/zeros)
#define VROWS 72
#define ATTN_SMEM (VB + 2*VROWS*RSTB)      // 47872 B

__global__ __launch_bounds__(128, 4) void attn_kernel()
{
    extern __shared__ char smc[];
    const int qt = gridDim.x - 1 - blockIdx.x;   // big CTAs first
    const int head = blockIdx.y, b = blockIdx.z;
    const int tid = threadIdx.x, wid = tid >> 5, lane = tid & 31;
    const int g = lane >> 2, j = lane & 3;
    const int r0 = wid * 32;
    const size_t base  = (size_t)(b * NHH + head) * SS * HDD;
    const size_t basev = (size_t)(b * NHH + head) * HDD * SS;
    const int q0 = qt * 128;
    const int rA = q0 + r0 + g, rB = rA + 8, rC = rA + 16, rD = rA + 24;

    const unsigned sbase = smem_u32(smc);

    // ones/zeros rows 64..71 of BOTH V buffers (row 64 = 1.0h, rest = 0)
    {
        unsigned* vrows = (unsigned*)(smc + VB);
        for (int idx = tid; idx < 2 * 8 * 44; idx += 128) {
            int buf = idx / (8 * 44);
            int rem = idx - buf * 8 * 44;
            int row = rem / 44, w = rem % 44;
            vrows[(buf * VROWS + 64 + row) * 44 + w] = (row == 0) ? 0x3C003C00u : 0u;
        }
    }

    // stage K/V tile 0
    #pragma unroll
    for (int i = 0; i < 4; i++) {
        int idx = tid + i * 128, r = idx >> 3, c8 = idx & 7;
        cp16(sbase + KB + r * RSTB + c8 * 16, &g_k[base + (size_t)r * HDD + c8 * 8]);
        cp16(sbase + VB + r * RSTB + c8 * 16, &g_vt[basev + (size_t)r * SS + c8 * 8]);
    }
    CP_COMMIT();

    // Q fragments straight from global (layout already permuted; one-time LDG.64s)
    uint2 qf[4][4];   // [row-group a,b,c,d][kg]
    #pragma unroll
    for (int kg = 0; kg < 4; kg++) {
        const int co = kg * 16 + 4 * j;
        qf[0][kg] = *(const uint2*)(g_q + base + (size_t)(q0 + r0 + g)      * HDD + co);
        qf[1][kg] = *(const uint2*)(g_q + base + (size_t)(q0 + r0 + g + 8)  * HDD + co);
        qf[2][kg] = *(const uint2*)(g_q + base + (size_t)(q0 + r0 + g + 16) * HDD + co);
        qf[3][kg] = *(const uint2*)(g_q + base + (size_t)(q0 + r0 + g + 24) * HDD + co);
    }

    const int ntiles = 2 * qt + 2;
    float oa0[9] = {}, oa1[9] = {}, oa2[9] = {}, oa3[9] = {};
    float ob0[9] = {}, ob1[9] = {}, ob2[9] = {}, ob3[9] = {};

    for (int kt = 0; kt < ntiles; kt++) {
        const int bf = kt & 1;
        CP_WAIT0();
        __syncthreads();                 // the only barrier in the loop

        if (kt + 1 < ntiles) {
            const int nb = bf ^ 1, k0n = (kt + 1) * 64;
            #pragma unroll
            for (int i = 0; i < 4; i++) {
                int idx = tid + i * 128, r = idx >> 3, c8 = idx & 7;
                cp16(sbase + KB + (nb * 64 + r) * RSTB + c8 * 16,
                     &g_k[base + (size_t)(k0n + r) * HDD + c8 * 8]);
                cp16(sbase + VB + (nb * VROWS + r) * RSTB + c8 * 16,
                     &g_vt[basev + (size_t)r * SS + k0n + c8 * 8]);
            }
            CP_COMMIT();
        }
        const int k0 = kt * 64;
        if (k0 > q0 + r0 + 31) continue;         // warp fully masked

        const char* Kb = smc + KB + bf * 64 * RSTB;
        const char* Vb = smc + VB + bf * VROWS * RSTB;
        const bool dmA = (k0 + 63) > (q0 + r0);
        const bool dmB = (k0 + 63) > (q0 + r0 + 16);

        // fused per nt-pair: S -> mask+exp -> PV (k-group p)
        #pragma unroll
        for (int p = 0; p < 4; p++) {
            float sa0[2] = {}, sa1[2] = {}, sa2[2] = {}, sa3[2] = {};
            float sb0[2] = {}, sb1[2] = {}, sb2[2] = {}, sb3[2] = {};
            #pragma unroll
            for (int kg = 0; kg < 4; kg++) {
                const int kb2 = (kg * 16 + 4 * j) * 2;
                #pragma unroll
                for (int u = 0; u < 2; u++) {
                    uint2 kv = *(const uint2*)(Kb + ((2 * p + u) * 8 + g) * RSTB + kb2);
                    mma_f16(sa0[u], sa1[u], sa2[u], sa3[u],
                            qf[0][kg].x, qf[1][kg].x, qf[0][kg].y, qf[1][kg].y,
                            kv.x, kv.y);
                    mma_f16(sb0[u], sb1[u], sb2[u], sb3[u],
                            qf[2][kg].x, qf[3][kg].x, qf[2][kg].y, qf[3][kg].y,
                            kv.x, kv.y);
                }
            }
            #pragma unroll
            for (int u = 0; u < 2; u++) {
                int col = k0 + (2 * p + u) * 8 + 2 * j;
                if (dmA) {
                    if (col     > rA) sa0[u] = -1.0e30f;
                    if (col + 1 > rA) sa1[u] = -1.0e30f;
                    if (col     > rB) sa2[u] = -1.0e30f;
                    if (col + 1 > rB) sa3[u] = -1.0e30f;
                }
                if (dmB) {
                    if (col     > rC) sb0[u] = -1.0e30f;
                    if (col + 1 > rC) sb1[u] = -1.0e30f;
                    if (col     > rD) sb2[u] = -1.0e30f;
                    if (col + 1 > rD) sb3[u] = -1.0e30f;
                }
            }
            unsigned a0 = ex2h2(pack_h2(sa0[0], sa1[0]));
            unsigned a2 = ex2h2(pack_h2(sa0[1], sa1[1]));
            unsigned a1 = ex2h2(pack_h2(sa2[0], sa3[0]));
            unsigned a3 = ex2h2(pack_h2(sa2[1], sa3[1]));
            unsigned c0 = ex2h2(pack_h2(sb0[0], sb1[0]));
            unsigned c2 = ex2h2(pack_h2(sb0[1], sb1[1]));
            unsigned c1 = ex2h2(pack_h2(sb2[0], sb3[0]));
            unsigned c3 = ex2h2(pack_h2(sb2[1], sb3[1]));

            const int kb2 = (p * 16 + 4 * j) * 2;
            #pragma unroll
            for (int nt = 0; nt < 9; nt++) {
                uint2 vv = *(const uint2*)(Vb + (nt * 8 + g) * RSTB + kb2);
                mma_f16(oa0[nt], oa1[nt], oa2[nt], oa3[nt],
                        a0, a1, a2, a3, vv.x, vv.y);
                mma_f16(ob0[nt], ob1[nt], ob2[nt], ob3[nt],
                        c0, c1, c2, c3, vv.x, vv.y);
            }
        }
    }

    // l lives in column 64 (nt=8, j=0 lanes): broadcast within each quad
    {
        const unsigned src = lane & ~3u;
        float lA = __shfl_sync(0xffffffffu, oa0[8], src);
        float lB = __shfl_sync(0xffffffffu, oa2[8], src);
        float lC = __shfl_sync(0xffffffffu, ob0[8], src);
        float lD = __shfl_sync(0xffffffffu, ob2[8], src);
        float liA = 1.0f / lA, liB = 1.0f / lB, liC = 1.0f / lC, liD = 1.0f / lD;
        __half* ga = (__half*)g_attn;
        #pragma unroll
        for (int nt = 0; nt < 8; nt++) {
            int col = nt * 8 + 2 * j;
            int poff = (col & ~15) + KPOS(col & 15);   // adjacent pair positions
            *(unsigned*)(ga + base + (size_t)rA * HDD + poff) =
                pack_h2(oa0[nt] * liA, oa1[nt] * liA);
            *(unsigned*)(ga + base + (size_t)rB * HDD + poff) =
                pack_h2(oa2[nt] * liB, oa3[nt] * liB);
            *(unsigned*)(ga + base + (size_t)rC * HDD + poff) =
                pack_h2(ob0[nt] * liC, ob1[nt] * liC);
            *(unsigned*)(ga + base + (size_t)rD * HDD + poff) =
                pack_h2(ob2[nt] * liD, ob3[nt] * liD);
        }
    }
}

// ---------------------------------------------------------------------------
extern "C" void kernel_launch(void* const* d_in, const int* in_sizes, int n_in,
                              void* d_out, int out_size)
{
    const float* hs = (const float*)d_in[0];
    // d_in[1] = attention_mask (fixed causal) -- handled analytically
    const float* wq = (const float*)d_in[2];
    const float* bq = (const float*)d_in[3];
    const float* wk = (const float*)d_in[4];
    const float* bk = (const float*)d_in[5];
    const float* wv = (const float*)d_in[6];
    const float* bv = (const float*)d_in[7];
    const float* wo = (const float*)d_in[8];
    const float* bo = (const float*)d_in[9];
    float* out = (float*)d_out;

    prep_kernel<<<(MM * KK / 16) / 256, 256>>>(hs);
    pre_round_w<<<dim3(KK / 32, HH / 32, 4), dim3(32, 8)>>>(wq, wk, wv, wo);

    cudaFuncSetAttribute(qkv_mma,  cudaFuncAttributeMaxDynamicSharedMemorySize, GEMM_SMEM);
    cudaFuncSetAttribute(proj_mma, cudaFuncAttributeMaxDynamicSharedMemorySize, GEMM_SMEM);
    cudaFuncSetAttribute(attn_kernel, cudaFuncAttributeMaxDynamicSharedMemorySize, ATTN_SMEM);

    qkv_mma<<<dim3(NHH / 2, 32, 3), 128, GEMM_SMEM>>>(bq, bk, bv);
    attn_kernel<<<dim3(SS / 128, NHH, BB), 128, ATTN_SMEM>>>();
    proj_mma<<<dim3(NHH / 2, 32), 128, GEMM_SMEM>>>(bo, out);
}

// round 17
// speedup vs baseline: 1.2599x; 1.2599x over previous
#include <cuda_runtime.h>
#include <cuda_fp16.h>
#include <math.h>

// ---------------------------------------------------------------------------
// Problem constants
// ---------------------------------------------------------------------------
#define BB   2
#define SS   2048
#define HH   1024
#define NHH  16
#define HDD  64
#define MM   (BB*SS)      // 4096
#define KK   1024

// k-permutation within each 16-group: thread j's m16n8k16 fragment halves
// {2j,2j+1,2j+8,2j+9} become contiguous -> single 8B load per fragment.
#define KPOS(k) ((((k)&6)<<1) + ((((k)>>3)&1)<<1) + ((k)&1))

// Scratch (device globals) — fp16, k-permuted where contracted
__device__ __half g_q[BB*NHH*SS*HDD];     // [b,h,s,d] d-permuted, pre-scaled
__device__ __half g_k[BB*NHH*SS*HDD];     // [b,h,s,d] d-permuted
__device__ __half g_vt[BB*NHH*HDD*SS];    // [b,h,d,s] s-permuted
__device__ __half g_attn[BB*NHH*SS*HDD];  // [b,h,s,d] d-permuted
__device__ __half g_hs[MM*KK];            // [m][k]    k-permuted
__device__ __half g_wqt[HH*KK];           // [n][k]    k-permuted
__device__ __half g_wkt[HH*KK];
__device__ __half g_wvt[HH*KK];
__device__ __half g_wot[HH*KK];
__device__ float  g_cost[SS*32];
__device__ float  g_sint[SS*32];

// ---------------------------------------------------------------------------
// Helpers
// ---------------------------------------------------------------------------
__device__ __forceinline__ unsigned pack_h2(float lo, float hi) {
    unsigned r;
    asm("cvt.rn.f16x2.f32 %0, %1, %2;" : "=r"(r) : "f"(hi), "f"(lo));
    return r;
}
__device__ __forceinline__ unsigned ex2h2(unsigned x) {
    unsigned r;
    asm("ex2.approx.f16x2 %0, %1;" : "=r"(r) : "r"(x));
    return r;
}
__device__ __forceinline__ void mma_f16(float& c0, float& c1, float& c2, float& c3,
                                        unsigned a0, unsigned a1, unsigned a2, unsigned a3,
                                        unsigned b0, unsigned b1) {
    asm volatile(
        "mma.sync.aligned.m16n8k16.row.col.f32.f16.f16.f32 "
        "{%0,%1,%2,%3}, {%4,%5,%6,%7}, {%8,%9}, {%0,%1,%2,%3};"
        : "+f"(c0), "+f"(c1), "+f"(c2), "+f"(c3)
        : "r"(a0), "r"(a1), "r"(a2), "r"(a3), "r"(b0), "r"(b1));
}
__device__ __forceinline__ unsigned smem_u32(const void* p) {
    unsigned a;
    asm("{ .reg .u64 t; cvta.to.shared.u64 t, %1; cvt.u32.u64 %0, t; }"
        : "=r"(a) : "l"(p));
    return a;
}
__device__ __forceinline__ void cp16(unsigned s, const void* g) {
    asm volatile("cp.async.cg.shared.global [%0], [%1], 16;" :: "r"(s), "l"(g));
}
#define CP_COMMIT() asm volatile("cp.async.commit_group;" ::: "memory")
#define CP_WAIT0()  asm volatile("cp.async.wait_group 0;" ::: "memory")

// ---------------------------------------------------------------------------
// Prep: hidden fp32 -> fp16 k-permuted; RoPE table
// ---------------------------------------------------------------------------
__global__ void prep_kernel(const float* __restrict__ hs) {
    int i = blockIdx.x * blockDim.x + threadIdx.x;   // 0..262143
    const float4* src = (const float4*)(hs + (size_t)i * 16);
    float4 v0 = src[0], v1 = src[1], v2 = src[2], v3 = src[3];
    uint4 o0, o1;
    o0.x = pack_h2(v0.x, v0.y);   // pos 0,1   = k0,1
    o0.y = pack_h2(v2.x, v2.y);   // pos 2,3   = k8,9
    o0.z = pack_h2(v0.z, v0.w);   // pos 4,5   = k2,3
    o0.w = pack_h2(v2.z, v2.w);   // pos 6,7   = k10,11
    o1.x = pack_h2(v1.x, v1.y);   // pos 8,9   = k4,5
    o1.y = pack_h2(v3.x, v3.y);   // pos 10,11 = k12,13
    o1.z = pack_h2(v1.z, v1.w);   // pos 12,13 = k6,7
    o1.w = pack_h2(v3.z, v3.w);   // pos 14,15 = k14,15
    uint4* dst = (uint4*)(g_hs + (size_t)i * 16);
    dst[0] = o0; dst[1] = o1;

    if (i < SS * 32) {
        int s = i >> 5, j = i & 31;
        float inv = expf(-((float)(2 * j) / 64.0f) * 9.210340371976184f);
        float ang = (float)s * inv;
        float c, sn;
        sincosf(ang, &sn, &c);
        g_cost[i] = c;
        g_sint[i] = sn;
    }
}

// ---------------------------------------------------------------------------
// Transpose + fp16 + k-permute the 4 weight matrices: [k][n] -> [n][k]
// ---------------------------------------------------------------------------
__global__ void pre_round_w(const float* __restrict__ wq, const float* __restrict__ wk,
                            const float* __restrict__ wv, const float* __restrict__ wo) {
    __shared__ float t[32][33];
    const int z = blockIdx.z;
    const float* src = (z == 0) ? wq : (z == 1) ? wk : (z == 2) ? wv : wo;
    __half* dst = (z == 0) ? g_wqt : (z == 1) ? g_wkt : (z == 2) ? g_wvt : g_wot;
    const int k0 = blockIdx.x * 32, n0 = blockIdx.y * 32;
    #pragma unroll
    for (int i = 0; i < 4; i++) {
        int ky = threadIdx.y + i * 8;
        t[ky][threadIdx.x] = src[(size_t)(k0 + ky) * HH + n0 + threadIdx.x];
    }
    __syncthreads();
    int kx = threadIdx.x;
    int kp = k0 + (kx & ~15) + KPOS(kx & 15);
    #pragma unroll
    for (int i = 0; i < 4; i++) {
        int ny = threadIdx.y + i * 8;
        dst[(size_t)(n0 + ny) * KK + kp] = __float2half_rn(t[kx][ny]);
    }
}

// ---------------------------------------------------------------------------
// fp16 mma GEMM (unchanged): 128x128 CTA tile (2 heads), k-chunk 64,
// 128 threads, 4 warps x (64x64), 2-stage cp.async, 128 MMAs per wait.
// ---------------------------------------------------------------------------
#define RSTB 176                          // row stride bytes (88 halves)
#define ASTAGE_B (128*RSTB)               // 22528
#define BSTAGE_B (128*RSTB)               // 22528
#define STAGE_B  (ASTAGE_B + BSTAGE_B)    // 45056
#define GEMM_SMEM (2 * STAGE_B)           // 90112
#define CST 132

__device__ __forceinline__ void gemm_chunk_f16(const char* As, const char* Bs,
                                               float acc[4][8][4],
                                               int wm, int wn, int g, int j) {
    #pragma unroll
    for (int kg = 0; kg < 4; kg++) {
        const int kb = (kg * 16 + 4 * j) * 2;
        uint2 a[4][2], bv[8];
        #pragma unroll
        for (int mt = 0; mt < 4; mt++) {
            int r = wm * 64 + mt * 16 + g;
            a[mt][0] = *(const uint2*)(As + r * RSTB + kb);
            a[mt][1] = *(const uint2*)(As + (r + 8) * RSTB + kb);
        }
        #pragma unroll
        for (int nt = 0; nt < 8; nt++) {
            int rr = wn * 64 + nt * 8 + g;
            bv[nt] = *(const uint2*)(Bs + rr * RSTB + kb);
        }
        #pragma unroll
        for (int mt = 0; mt < 4; mt++)
            #pragma unroll
            for (int nt = 0; nt < 8; nt++)
                mma_f16(acc[mt][nt][0], acc[mt][nt][1], acc[mt][nt][2], acc[mt][nt][3],
                        a[mt][0].x, a[mt][1].x, a[mt][0].y, a[mt][1].y,
                        bv[nt].x, bv[nt].y);
    }
}

// which: 0=q(rope,scaled) 1=k(rope) 2=v(transposed). n-tile = TWO heads.
__global__ __launch_bounds__(128) void qkv_mma(
    const float* __restrict__ bq, const float* __restrict__ bk, const float* __restrict__ bv)
{
    extern __shared__ char smc[];
    const int which = blockIdx.z;
    const __half* WT  = (which == 0) ? g_wqt : (which == 1) ? g_wkt : g_wvt;
    const float* bias = (which == 0) ? bq    : (which == 1) ? bk    : bv;

    const int head0 = blockIdx.x * 2;
    const int n0 = head0 * 64, m0 = blockIdx.y * 128;
    const int tid = threadIdx.x, wid = tid >> 5, lane = tid & 31;
    const int g = lane >> 2, j = lane & 3;
    const int wm = wid & 1, wn = wid >> 1;
    const unsigned sb = smem_u32(smc);

    auto stage = [&](int c) {
        const int k0 = c * 64;
        const unsigned bufb = sb + (c & 1) * STAGE_B;
        #pragma unroll
        for (int i = 0; i < 8; i++) {
            int idx = tid + i * 128, r = idx >> 3, c8 = idx & 7;
            cp16(bufb + r * RSTB + c8 * 16, &g_hs[(size_t)(m0 + r) * KK + k0 + c8 * 8]);
        }
        #pragma unroll
        for (int i = 0; i < 8; i++) {
            int idx = tid + i * 128, r = idx >> 3, c8 = idx & 7;
            cp16(bufb + ASTAGE_B + r * RSTB + c8 * 16,
                 &WT[(size_t)(n0 + r) * KK + k0 + c8 * 8]);
        }
        CP_COMMIT();
    };

    float acc[4][8][4] = {};
    stage(0);
    for (int c = 0; c < 16; c++) {
        CP_WAIT0();
        __syncthreads();
        if (c < 15) stage(c + 1);
        const char* As = smc + (c & 1) * STAGE_B;
        gemm_chunk_f16(As, As + ASTAGE_B, acc, wm, wn, g, j);
    }
    __syncthreads();

    float* Cs = (float*)smc;
    #pragma unroll
    for (int mt = 0; mt < 4; mt++)
        #pragma unroll
        for (int nt = 0; nt < 8; nt++) {
            int r = wm * 64 + mt * 16 + g, cc = wn * 64 + nt * 8 + 2 * j;
            *(float2*)&Cs[r * CST + cc]       = make_float2(acc[mt][nt][0], acc[mt][nt][1]);
            *(float2*)&Cs[(r + 8) * CST + cc] = make_float2(acc[mt][nt][2], acc[mt][nt][3]);
        }
    __syncthreads();

    const float QSCALE = 0.125f * 1.4426950408889634f;
    if (which != 2) {
        __half* out = (which == 0) ? g_q : g_k;
        const float scale = (which == 0) ? QSCALE : 1.0f;
        #pragma unroll 4
        for (int it = 0; it < 64; it++) {
            int p = it * 128 + tid;          // 128 rows x 64 pairs
            int r = p >> 6, hh = (p >> 5) & 1, jj = p & 31;
            int m = m0 + r, bb = m >> 11, s = m & 2047;
            int head = head0 + hh;
            float x1 = Cs[r * CST + hh * 64 + jj]      + bias[head * 64 + jj];
            float x2 = Cs[r * CST + hh * 64 + jj + 32] + bias[head * 64 + jj + 32];
            float cs = g_cost[s * 32 + jj], sn = g_sint[s * 32 + jj];
            __half* op = out + ((size_t)(bb * NHH + head) * SS + s) * HDD;
            int d1 = jj, d2 = jj + 32;
            op[(d1 & ~15) + KPOS(d1 & 15)] = __float2half_rn((x1 * cs - x2 * sn) * scale);
            op[(d2 & ~15) + KPOS(d2 & 15)] = __float2half_rn((x1 * sn + x2 * cs) * scale);
        }
    } else {
        #pragma unroll 4
        for (int it = 0; it < 128; it++) {
            int p = it * 128 + tid;          // 128 cols x 128 rows
            int r = p & 127, cc = p >> 7;
            int m = m0 + r, bb = m >> 11, s = m & 2047;
            int head = head0 + (cc >> 6), d = cc & 63;
            int spos = (s & ~15) + KPOS(s & 15);
            g_vt[((size_t)(bb * NHH + head) * HDD + d) * SS + spos] =
                __float2half_rn(Cs[r * CST + cc] + bias[head * 64 + d]);
        }
    }
}

__global__ __launch_bounds__(128) void proj_mma(
    const float* __restrict__ bo, float* __restrict__ outp)
{
    extern __shared__ char smc[];
    const int n0 = blockIdx.x * 128, m0 = blockIdx.y * 128;
    const int tid = threadIdx.x, wid = tid >> 5, lane = tid & 31;
    const int g = lane >> 2, j = lane & 3;
    const int wm = wid & 1, wn = wid >> 1;
    const unsigned sb = smem_u32(smc);

    auto stage = [&](int c) {
        const unsigned bufb = sb + (c & 1) * STAGE_B;
        #pragma unroll
        for (int i = 0; i < 8; i++) {
            int idx = tid + i * 128, r = idx >> 3, c8 = idx & 7;
            int m = m0 + r, bb = m >> 11, s = m & 2047;
            cp16(bufb + r * RSTB + c8 * 16,
                 &g_attn[((size_t)(bb * NHH + c) * SS + s) * HDD + c8 * 8]);
        }
        #pragma unroll
        for (int i = 0; i < 8; i++) {
            int idx = tid + i * 128, r = idx >> 3, c8 = idx & 7;
            cp16(bufb + ASTAGE_B + r * RSTB + c8 * 16,
                 &g_wot[(size_t)(n0 + r) * KK + c * 64 + c8 * 8]);
        }
        CP_COMMIT();
    };

    float acc[4][8][4] = {};
    stage(0);
    for (int c = 0; c < 16; c++) {
        CP_WAIT0();
        __syncthreads();
        if (c < 15) stage(c + 1);
        const char* As = smc + (c & 1) * STAGE_B;
        gemm_chunk_f16(As, As + ASTAGE_B, acc, wm, wn, g, j);
    }
    __syncthreads();

    float* Cs = (float*)smc;
    #pragma unroll
    for (int mt = 0; mt < 4; mt++)
        #pragma unroll
        for (int nt = 0; nt < 8; nt++) {
            int r = wm * 64 + mt * 16 + g, cc = wn * 64 + nt * 8 + 2 * j;
            *(float2*)&Cs[r * CST + cc]       = make_float2(acc[mt][nt][0], acc[mt][nt][1]);
            *(float2*)&Cs[(r + 8) * CST + cc] = make_float2(acc[mt][nt][2], acc[mt][nt][3]);
        }
    __syncthreads();

    #pragma unroll 4
    for (int i = 0; i < 32; i++) {
        int idx = tid + i * 128;             // 128 rows x 32 float4
        int r = idx >> 5, c4 = idx & 31;
        float4 v = *(float4*)&Cs[r * CST + c4 * 4];
        float4 bv = *(const float4*)&bo[n0 + c4 * 4];
        v.x += bv.x; v.y += bv.y; v.z += bv.z; v.w += bv.w;
        *(float4*)&outp[(size_t)(m0 + r) * HH + n0 + c4 * 4] = v;
    }
}

// ---------------------------------------------------------------------------
// Flash attention fp16 v4: global-Q fragments (no Q smem, 47.9KB total),
// fused S->exp->PV, tensor-core l, f16x2 exp. __launch_bounds__(128,3):
// ~170-reg budget -> NO spills (R16's 128-cap spilled and regressed).
// ---------------------------------------------------------------------------
#define KB 0                               // K: 2 x 64 rows
#define VB (2*64*RSTB)                     // V: 2 x 72 rows (64 data + ones/zeros)
#define VROWS 72
#define ATTN_SMEM (VB + 2*VROWS*RSTB)      // 47872 B

__global__ __launch_bounds__(128, 3) void attn_kernel()
{
    extern __shared__ char smc[];
    const int qt = gridDim.x - 1 - blockIdx.x;   // big CTAs first
    const int head = blockIdx.y, b = blockIdx.z;
    const int tid = threadIdx.x, wid = tid >> 5, lane = tid & 31;
    const int g = lane >> 2, j = lane & 3;
    const int r0 = wid * 32;
    const size_t base  = (size_t)(b * NHH + head) * SS * HDD;
    const size_t basev = (size_t)(b * NHH + head) * HDD * SS;
    const int q0 = qt * 128;
    const int rA = q0 + r0 + g, rB = rA + 8, rC = rA + 16, rD = rA + 24;

    const unsigned sbase = smem_u32(smc);

    // ones/zeros rows 64..71 of BOTH V buffers (row 64 = 1.0h, rest = 0)
    {
        unsigned* vrows = (unsigned*)(smc + VB);
        for (int idx = tid; idx < 2 * 8 * 44; idx += 128) {
            int buf = idx / (8 * 44);
            int rem = idx - buf * 8 * 44;
            int row = rem / 44, w = rem % 44;
            vrows[(buf * VROWS + 64 + row) * 44 + w] = (row == 0) ? 0x3C003C00u : 0u;
        }
    }

    // stage K/V tile 0
    #pragma unroll
    for (int i = 0; i < 4; i++) {
        int idx = tid + i * 128, r = idx >> 3, c8 = idx & 7;
        cp16(sbase + KB + r * RSTB + c8 * 16, &g_k[base + (size_t)r * HDD + c8 * 8]);
        cp16(sbase + VB + r * RSTB + c8 * 16, &g_vt[basev + (size_t)r * SS + c8 * 8]);
    }
    CP_COMMIT();

    // Q fragments straight from global (layout already permuted; one-time LDG.64s)
    uint2 qf[4][4];   // [row-group a,b,c,d][kg]
    #pragma unroll
    for (int kg = 0; kg < 4; kg++) {
        const int co = kg * 16 + 4 * j;
        qf[0][kg] = *(const uint2*)(g_q + base + (size_t)(q0 + r0 + g)      * HDD + co);
        qf[1][kg] = *(const uint2*)(g_q + base + (size_t)(q0 + r0 + g + 8)  * HDD + co);
        qf[2][kg] = *(const uint2*)(g_q + base + (size_t)(q0 + r0 + g + 16) * HDD + co);
        qf[3][kg] = *(const uint2*)(g_q + base + (size_t)(q0 + r0 + g + 24) * HDD + co);
    }

    const int ntiles = 2 * qt + 2;
    float oa0[9] = {}, oa1[9] = {}, oa2[9] = {}, oa3[9] = {};
    float ob0[9] = {}, ob1[9] = {}, ob2[9] = {}, ob3[9] = {};

    for (int kt = 0; kt < ntiles; kt++) {
        const int bf = kt & 1;
        CP_WAIT0();
        __syncthreads();                 // the only barrier in the loop

        if (kt + 1 < ntiles) {
            const int nb = bf ^ 1, k0n = (kt + 1) * 64;
            #pragma unroll
            for (int i = 0; i < 4; i++) {
                int idx = tid + i * 128, r = idx >> 3, c8 = idx & 7;
                cp16(sbase + KB + (nb * 64 + r) * RSTB + c8 * 16,
                     &g_k[base + (size_t)(k0n + r) * HDD + c8 * 8]);
                cp16(sbase + VB + (nb * VROWS + r) * RSTB + c8 * 16,
                     &g_vt[basev + (size_t)r * SS + k0n + c8 * 8]);
            }
            CP_COMMIT();
        }
        const int k0 = kt * 64;
        if (k0 > q0 + r0 + 31) continue;         // warp fully masked

        const char* Kb = smc + KB + bf * 64 * RSTB;
        const char* Vb = smc + VB + bf * VROWS * RSTB;
        const bool dmA = (k0 + 63) > (q0 + r0);
        const bool dmB = (k0 + 63) > (q0 + r0 + 16);

        // fused per nt-pair: S -> mask+exp -> PV (k-group p)
        #pragma unroll
        for (int p = 0; p < 4; p++) {
            float sa0[2] = {}, sa1[2] = {}, sa2[2] = {}, sa3[2] = {};
            float sb0[2] = {}, sb1[2] = {}, sb2[2] = {}, sb3[2] = {};
            #pragma unroll
            for (int kg = 0; kg < 4; kg++) {
                const int kb2 = (kg * 16 + 4 * j) * 2;
                #pragma unroll
                for (int u = 0; u < 2; u++) {
                    uint2 kv = *(const uint2*)(Kb + ((2 * p + u) * 8 + g) * RSTB + kb2);
                    mma_f16(sa0[u], sa1[u], sa2[u], sa3[u],
                            qf[0][kg].x, qf[1][kg].x, qf[0][kg].y, qf[1][kg].y,
                            kv.x, kv.y);
                    mma_f16(sb0[u], sb1[u], sb2[u], sb3[u],
                            qf[2][kg].x, qf[3][kg].x, qf[2][kg].y, qf[3][kg].y,
                            kv.x, kv.y);
                }
            }
            #pragma unroll
            for (int u = 0; u < 2; u++) {
                int col = k0 + (2 * p + u) * 8 + 2 * j;
                if (dmA) {
                    if (col     > rA) sa0[u] = -1.0e30f;
                    if (col + 1 > rA) sa1[u] = -1.0e30f;
                    if (col     > rB) sa2[u] = -1.0e30f;
                    if (col + 1 > rB) sa3[u] = -1.0e30f;
                }
                if (dmB) {
                    if (col     > rC) sb0[u] = -1.0e30f;
                    if (col + 1 > rC) sb1[u] = -1.0e30f;
                    if (col     > rD) sb2[u] = -1.0e30f;
                    if (col + 1 > rD) sb3[u] = -1.0e30f;
                }
            }
            unsigned a0 = ex2h2(pack_h2(sa0[0], sa1[0]));
            unsigned a2 = ex2h2(pack_h2(sa0[1], sa1[1]));
            unsigned a1 = ex2h2(pack_h2(sa2[0], sa3[0]));
            unsigned a3 = ex2h2(pack_h2(sa2[1], sa3[1]));
            unsigned c0 = ex2h2(pack_h2(sb0[0], sb1[0]));
            unsigned c2 = ex2h2(pack_h2(sb0[1], sb1[1]));
            unsigned c1 = ex2h2(pack_h2(sb2[0], sb3[0]));
            unsigned c3 = ex2h2(pack_h2(sb2[1], sb3[1]));

            const int kb2 = (p * 16 + 4 * j) * 2;
            #pragma unroll
            for (int nt = 0; nt < 9; nt++) {
                uint2 vv = *(const uint2*)(Vb + (nt * 8 + g) * RSTB + kb2);
                mma_f16(oa0[nt], oa1[nt], oa2[nt], oa3[nt],
                        a0, a1, a2, a3, vv.x, vv.y);
                mma_f16(ob0[nt], ob1[nt], ob2[nt], ob3[nt],
                        c0, c1, c2, c3, vv.x, vv.y);
            }
        }
    }

    // l lives in column 64 (nt=8, j=0 lanes): broadcast within each quad
    {
        const unsigned src = lane & ~3u;
        float lA = __shfl_sync(0xffffffffu, oa0[8], src);
        float lB = __shfl_sync(0xffffffffu, oa2[8], src);
        float lC = __shfl_sync(0xffffffffu, ob0[8], src);
        float lD = __shfl_sync(0xffffffffu, ob2[8], src);
        float liA = 1.0f / lA, liB = 1.0f / lB, liC = 1.0f / lC, liD = 1.0f / lD;
        __half* ga = (__half*)g_attn;
        #pragma unroll
        for (int nt = 0; nt < 8; nt++) {
            int col = nt * 8 + 2 * j;
            int poff = (col & ~15) + KPOS(col & 15);   // adjacent pair positions
            *(unsigned*)(ga + base + (size_t)rA * HDD + poff) =
                pack_h2(oa0[nt] * liA, oa1[nt] * liA);
            *(unsigned*)(ga + base + (size_t)rB * HDD + poff) =
                pack_h2(oa2[nt] * liB, oa3[nt] * liB);
            *(unsigned*)(ga + base + (size_t)rC * HDD + poff) =
                pack_h2(ob0[nt] * liC, ob1[nt] * liC);
            *(unsigned*)(ga + base + (size_t)rD * HDD + poff) =
                pack_h2(ob2[nt] * liD, ob3[nt] * liD);
        }
    }
}

// ---------------------------------------------------------------------------
extern "C" void kernel_launch(void* const* d_in, const int* in_sizes, int n_in,
                              void* d_out, int out_size)
{
    const float* hs = (const float*)d_in[0];
    // d_in[1] = attention_mask (fixed causal) -- handled analytically
    const float* wq = (const float*)d_in[2];
    const float* bq = (const float*)d_in[3];
    const float* wk = (const float*)d_in[4];
    const float* bk = (const float*)d_in[5];
    const float* wv = (const float*)d_in[6];
    const float* bv = (const float*)d_in[7];
    const float* wo = (const float*)d_in[8];
    const float* bo = (const float*)d_in[9];
    float* out = (float*)d_out;

    prep_kernel<<<(MM * KK / 16) / 256, 256>>>(hs);
    pre_round_w<<<dim3(KK / 32, HH / 32, 4), dim3(32, 8)>>>(wq, wk, wv, wo);

    cudaFuncSetAttribute(qkv_mma,  cudaFuncAttributeMaxDynamicSharedMemorySize, GEMM_SMEM);
    cudaFuncSetAttribute(proj_mma, cudaFuncAttributeMaxDynamicSharedMemorySize, GEMM_SMEM);
    cudaFuncSetAttribute(attn_kernel, cudaFuncAttributeMaxDynamicSharedMemorySize, ATTN_SMEM);

    qkv_mma<<<dim3(NHH / 2, 32, 3), 128, GEMM_SMEM>>>(bq, bk, bv);
    attn_kernel<<<dim3(SS / 128, NHH, BB), 128, ATTN_SMEM>>>();
    proj_mma<<<dim3(NHH / 2, 32), 128, GEMM_SMEM>>>(bo, out);
}